// round 9
// baseline (speedup 1.0000x reference)
#include <cuda_runtime.h>
#include <stdint.h>

// ---------------------------------------------------------------------------
// RollingHashPyramid:
//   keys[s](b,t) = (XOR_{i<W_s} tokens[b,t-1-i] * P_s[i]) mod 65536
//   short  = tables[s][keys[s]], s=0..3  -> logits = concat(short) @ Wc^T
//   cond   = XOR of BASE[j] over j with logit_j > 0  (low 16 bits matter)
//   long   = tables[s][(keys[s]^cond) & 0xFFFF], s=4..7
//   out[b,t,s,:] = gathered rows.
// All hash math in u32 (low 16 bits of int64 products match).
// Token buffer layout (int64 vs int32) is detected at runtime.
// ---------------------------------------------------------------------------

__device__ __forceinline__ constexpr unsigned BASE(int i) {
    constexpr unsigned a[16] = {
        2654435761u, 2246822519u, 3266489917u, 2028178513u,
        1220703125u, 1610612741u,  805306457u,  402653189u,
        3674653429u, 2860486313u, 1073676287u, 2971215073u,
        1500450271u, 3267000013u, 2654435789u, 4049292737u };
    return a[i];
}
__device__ __forceinline__ constexpr unsigned EXTRA(int i) {
    constexpr unsigned a[16] = {
        2246822531u, 3266489927u, 2028178519u, 1220703133u,
        1610612759u,  805306463u,  402653201u, 3674653441u,
        2860486319u, 1073676311u, 2971215091u, 1500450277u,
        3267000023u, 2654435801u, 4049292751u, 2246822537u };
    return a[i];
}
__device__ __forceinline__ constexpr unsigned C5(int i) {
    return ((i < 16) ? BASE(i) : EXTRA(i - 16)) ^ 3735928559u;  // ^0xDEADBEEF
}
__device__ __forceinline__ constexpr unsigned C6(int k) {
    return BASE(k) ^ 3405691582u;  // ^0xCAFEBABE
}
__device__ __forceinline__ constexpr unsigned C7(int k) {
    return BASE(k) ^ 2343432205u;  // ^0x8BADF00D
}

// Scratch: proj[s][bucket][j] = sum_e tables[s][bucket][e] * Wc[j][s*16+e]
__device__ float d_proj[4 * 65536 * 8];   // 8 MB
__device__ unsigned d_tok_stride;          // 2 if tokens are int64, 1 if int32

// ---------------------------------------------------------------------------
// Kernel 0: detect token element width. int64 tokens (< 1024) have all-zero
// high words at odd int32 indices; int32 tokens there are random in [0,1024).
// ---------------------------------------------------------------------------
__global__ void rhp_detect(const unsigned* __restrict__ tok)
{
    unsigned any = 0;
    for (int i = threadIdx.x; i < 2048; i += 32)
        any |= tok[2 * i + 1];
    any = __ballot_sync(0xFFFFFFFFu, any != 0);
    if (threadIdx.x == 0) d_tok_stride = any ? 1u : 2u;
}

// ---------------------------------------------------------------------------
// Kernel 1: project the 4 short tables through Wc once per bucket.
// 262144 rows, one thread per row. Wc (512 floats) staged in shared.
// Accumulate in double to minimize sign-flip risk vs the fp32 reference.
// ---------------------------------------------------------------------------
__global__ __launch_bounds__(256) void rhp_proj(
    const float* __restrict__ tables, const float* __restrict__ Wc)
{
    __shared__ float swc[512];  // Wc[8][64]
    int tid = threadIdx.x;
    if (tid < 128) ((float4*)swc)[tid] = ((const float4*)Wc)[tid];
    __syncthreads();

    int row = blockIdx.x * 256 + tid;      // row = s*65536 + bucket, s in 0..3
    int s = row >> 16;
    const float4* t4 = (const float4*)tables + (size_t)row * 4;
    float4 r0 = t4[0], r1 = t4[1], r2 = t4[2], r3 = t4[3];
    float r[16] = { r0.x, r0.y, r0.z, r0.w, r1.x, r1.y, r1.z, r1.w,
                    r2.x, r2.y, r2.z, r2.w, r3.x, r3.y, r3.z, r3.w };

    float o[8];
#pragma unroll
    for (int j = 0; j < 8; j++) {
        const float* w = &swc[j * 64 + s * 16];
        double acc = 0.0;
#pragma unroll
        for (int e = 0; e < 16; e++)
            acc += (double)r[e] * (double)w[e];
        o[j] = (float)acc;
    }
    float4* p = ((float4*)d_proj) + (size_t)row * 2;
    p[0] = make_float4(o[0], o[1], o[2], o[3]);
    p[1] = make_float4(o[4], o[5], o[6], o[7]);
}

// ---------------------------------------------------------------------------
// Kernel 2: main. 256 positions per block (one thread per position for the
// hash), then warp-remapped coalesced gather+store (one warp writes one
// position's contiguous 512B per iteration).
// ---------------------------------------------------------------------------
__global__ __launch_bounds__(256) void rhp_main(
    const unsigned* __restrict__ tok,      // raw int32 view of token buffer
    const float* __restrict__ tables,
    float* __restrict__ out)
{
    __shared__ unsigned stok[384];         // tokens [t0-128, t0+256)
    __shared__ unsigned short skey[256 * 8];

    int tid = threadIdx.x;
    int b   = blockIdx.x >> 4;             // 32 rows
    int t0  = (blockIdx.x & 15) << 8;      // 16 chunks of 256
    unsigned rowbase = (unsigned)b * 4096u;
    unsigned stride = d_tok_stride;        // 1 (int32) or 2 (int64)

    // ---- token staging ------------------------------------------------------
    for (int i = tid; i < 384; i += 256) {
        int t = t0 - 128 + i;
        unsigned v = 0;
        if (t >= 0) v = tok[stride * (rowbase + (unsigned)t)];
        stok[i] = v;
    }
    __syncthreads();

    // ---- per-position hashing (each token loaded once) ----------------------
    unsigned hs = 0, h5 = 0, h6 = 0, h7 = 0;
    unsigned k0 = 0, k1 = 0, k2 = 0, k3 = 0, k4 = 0;
    int basei = 127 + tid;                 // stok index of token at t-1
#pragma unroll
    for (int i = 0; i < 128; i++) {
        unsigned tk = stok[basei - i];
        h7 ^= tk * C7(i & 7);
        if (i < 64) h6 ^= tk * C6(i & 7);
        if (i < 32) h5 ^= tk * C5(i);
        if (i < 16) {
            hs ^= tk * BASE(i);
            if (i == 0)  k0 = hs;
            if (i == 1)  k1 = hs;
            if (i == 3)  k2 = hs;
            if (i == 7)  k3 = hs;
            if (i == 15) k4 = hs;
        }
    }
    k0 &= 0xFFFFu; k1 &= 0xFFFFu; k2 &= 0xFFFFu; k3 &= 0xFFFFu; k4 &= 0xFFFFu;
    unsigned k5 = h5 & 0xFFFFu, k6 = h6 & 0xFFFFu, k7 = h7 & 0xFFFFu;

    // ---- conditioning logits via precomputed projections ---------------------
    float lg0 = 0.f, lg1 = 0.f, lg2 = 0.f, lg3 = 0.f;
    float lg4 = 0.f, lg5 = 0.f, lg6 = 0.f, lg7 = 0.f;
    unsigned ks[4] = { k0, k1, k2, k3 };
#pragma unroll
    for (int s = 0; s < 4; s++) {
        const float4* p = ((const float4*)d_proj) + ((size_t)((s << 16) + ks[s])) * 2;
        float4 a = p[0], c = p[1];
        lg0 += a.x; lg1 += a.y; lg2 += a.z; lg3 += a.w;
        lg4 += c.x; lg5 += c.y; lg6 += c.z; lg7 += c.w;
    }
    unsigned cond = 0;
    if (lg0 > 0.f) cond ^= BASE(0);
    if (lg1 > 0.f) cond ^= BASE(1);
    if (lg2 > 0.f) cond ^= BASE(2);
    if (lg3 > 0.f) cond ^= BASE(3);
    if (lg4 > 0.f) cond ^= BASE(4);
    if (lg5 > 0.f) cond ^= BASE(5);
    if (lg6 > 0.f) cond ^= BASE(6);
    if (lg7 > 0.f) cond ^= BASE(7);
    cond &= 0xFFFFu;

    uint4 packed;
    packed.x = k0 | (k1 << 16);
    packed.y = k2 | (k3 << 16);
    packed.z = (k4 ^ cond) | ((k5 ^ cond) << 16);
    packed.w = (k6 ^ cond) | ((k7 ^ cond) << 16);
    ((uint4*)skey)[tid] = packed;
    __syncthreads();

    // ---- coalesced gather + store --------------------------------------------
    // Warp w, iteration iter -> position p = iter*8 + w.
    // Lane l: s = l>>2, q = l&3. Warp writes 512 contiguous bytes per iter.
    const float4* tab4 = (const float4*)tables;
    float4* out4 = (float4*)out;
    size_t obase = ((size_t)(rowbase + (unsigned)t0)) * 32;  // float4 units
    int lane = tid & 31;
    int w    = tid >> 5;
    int s    = lane >> 2;
    int q    = lane & 3;
#pragma unroll 8
    for (int iter = 0; iter < 32; iter++) {
        int p = (iter << 3) + w;
        unsigned key = skey[p * 8 + s];
        float4 v = tab4[((size_t)((s << 16) + key) << 2) + q];
        out4[obase + (size_t)p * 32 + lane] = v;
    }
}

extern "C" void kernel_launch(void* const* d_in, const int* in_sizes, int n_in,
                              void* d_out, int out_size)
{
    const unsigned* tokens = (const unsigned*)d_in[0];
    const float*    tables = (const float*)d_in[1];
    const float*    Wc     = (const float*)d_in[2];
    float*          out    = (float*)d_out;

    rhp_detect<<<1, 32>>>(tokens);
    rhp_proj<<<1024, 256>>>(tables, Wc);          // 4*65536 rows / 256
    rhp_main<<<512, 256>>>(tokens, tables, out);  // 32 rows * 16 chunks
}

// round 10
// speedup vs baseline: 1.0228x; 1.0228x over previous
#include <cuda_runtime.h>
#include <stdint.h>

// ---------------------------------------------------------------------------
// RollingHashPyramid:
//   keys[s](b,t) = (XOR_{i<W_s} tokens[b,t-1-i] * P_s[i]) mod 65536
//   short  = tables[s][keys[s]], s=0..3  -> logits = concat(short) @ Wc^T
//   cond   = XOR of BASE[j] over j with logit_j > 0  (low 16 bits matter)
//   long   = tables[s][(keys[s]^cond) & 0xFFFF], s=4..7
//   out[b,t,s,:] = gathered rows.
// Scales 6/7 use primes periodic mod 8 -> factor into 8-token block hashes
// F6/F7 shared across positions (h7 = XOR of 16 blocks, h6 = XOR of 8).
// ---------------------------------------------------------------------------

__device__ __forceinline__ constexpr unsigned BASE(int i) {
    constexpr unsigned a[16] = {
        2654435761u, 2246822519u, 3266489917u, 2028178513u,
        1220703125u, 1610612741u,  805306457u,  402653189u,
        3674653429u, 2860486313u, 1073676287u, 2971215073u,
        1500450271u, 3267000013u, 2654435789u, 4049292737u };
    return a[i];
}
__device__ __forceinline__ constexpr unsigned EXTRA(int i) {
    constexpr unsigned a[16] = {
        2246822531u, 3266489927u, 2028178519u, 1220703133u,
        1610612759u,  805306463u,  402653201u, 3674653441u,
        2860486319u, 1073676311u, 2971215091u, 1500450277u,
        3267000023u, 2654435801u, 4049292751u, 2246822537u };
    return a[i];
}
__device__ __forceinline__ constexpr unsigned C5(int i) {
    return ((i < 16) ? BASE(i) : EXTRA(i - 16)) ^ 3735928559u;  // ^0xDEADBEEF
}
__device__ __forceinline__ constexpr unsigned C6(int k) {
    return BASE(k) ^ 3405691582u;  // ^0xCAFEBABE
}
__device__ __forceinline__ constexpr unsigned C7(int k) {
    return BASE(k) ^ 2343432205u;  // ^0x8BADF00D
}

// Scratch: proj[s][bucket][j] = sum_e tables[s][bucket][e] * Wc[j][s*16+e]
__device__ float d_proj[4 * 65536 * 8];   // 8 MB
__device__ unsigned d_tok_stride;          // 2 if tokens are int64, 1 if int32

// ---------------------------------------------------------------------------
// Kernel 0: detect token element width (parallel, ~1us).
// int64 tokens (<1024) have zero high words at odd int32 indices; int32
// tokens there are random in [0,1024): P(1024 words all zero) ~ 0.
// ---------------------------------------------------------------------------
__global__ __launch_bounds__(256) void rhp_detect(const unsigned* __restrict__ tok)
{
    unsigned any = 0;
#pragma unroll
    for (int r = 0; r < 4; r++)
        any |= tok[2 * (threadIdx.x + 256 * r) + 1];
    int blk = __syncthreads_or(any != 0);
    if (threadIdx.x == 0) d_tok_stride = blk ? 1u : 2u;
}

// ---------------------------------------------------------------------------
// Kernel 1: project the 4 short tables through Wc once per bucket.
// 262144 rows, one thread per row. Double accumulation (sign-exact vs ref).
// ---------------------------------------------------------------------------
__global__ __launch_bounds__(256) void rhp_proj(
    const float* __restrict__ tables, const float* __restrict__ Wc)
{
    __shared__ float swc[512];  // Wc[8][64]
    int tid = threadIdx.x;
    if (tid < 128) ((float4*)swc)[tid] = ((const float4*)Wc)[tid];
    __syncthreads();

    int row = blockIdx.x * 256 + tid;      // row = s*65536 + bucket, s in 0..3
    int s = row >> 16;
    const float4* t4 = (const float4*)tables + (size_t)row * 4;
    float4 r0 = t4[0], r1 = t4[1], r2 = t4[2], r3 = t4[3];
    float r[16] = { r0.x, r0.y, r0.z, r0.w, r1.x, r1.y, r1.z, r1.w,
                    r2.x, r2.y, r2.z, r2.w, r3.x, r3.y, r3.z, r3.w };

    float o[8];
#pragma unroll
    for (int j = 0; j < 8; j++) {
        const float* w = &swc[j * 64 + s * 16];
        double acc = 0.0;
#pragma unroll
        for (int e = 0; e < 16; e++)
            acc += (double)r[e] * (double)w[e];
        o[j] = (float)acc;
    }
    float4* p = ((float4*)d_proj) + (size_t)row * 2;
    p[0] = make_float4(o[0], o[1], o[2], o[3]);
    p[1] = make_float4(o[4], o[5], o[6], o[7]);
}

// ---------------------------------------------------------------------------
// Kernel 2: main. 512 positions per block, one thread per position.
// Scales 0-5 hashed directly (48 IMAD); scales 6/7 via shared F6/F7 block
// hashes (16 IMAD + LDS XORs). Then warp-remapped coalesced gather+store.
// ---------------------------------------------------------------------------
#define POS 512
#define HALO_F 120          // F7 needed down to t-120
__global__ __launch_bounds__(POS) void rhp_main(
    const unsigned* __restrict__ tok,      // raw int32 view of token buffer
    const float* __restrict__ tables,
    float* __restrict__ out)
{
    __shared__ unsigned stok[POS + 128];           // tokens [t0-128, t0+POS)
    __shared__ unsigned sF6[POS + HALO_F];         // F6(t), t in [t0-120, t0+POS)
    __shared__ unsigned sF7[POS + HALO_F];
    __shared__ unsigned short skey[POS * 8];

    int tid = threadIdx.x;
    int b   = blockIdx.x >> 3;             // 32 rows
    int t0  = (blockIdx.x & 7) << 9;       // 8 chunks of 512
    unsigned rowbase = (unsigned)b * 4096u;
    unsigned stride = d_tok_stride;        // 1 (int32) or 2 (int64)

    // ---- token staging ------------------------------------------------------
    for (int i = tid; i < POS + 128; i += POS) {
        int t = t0 - 128 + i;
        unsigned v = 0;
        if (t >= 0) v = tok[stride * (rowbase + (unsigned)t)];
        stok[i] = v;
    }
    __syncthreads();

    // ---- F6/F7 block hashes: F(t) = XOR_{r<8} tok(t-1-r)*C(r) ---------------
    // ft indexes t = (t0 - HALO_F) + ft; tokens are stok[ft .. ft+7].
    for (int ft = tid; ft < POS + HALO_F; ft += POS) {
        unsigned f6 = 0, f7 = 0;
#pragma unroll
        for (int q = 0; q < 8; q++) {
            unsigned tk = stok[ft + q];    // token at t-1-r with r = 7-q
            f6 ^= tk * C6(7 - q);
            f7 ^= tk * C7(7 - q);
        }
        sF6[ft] = f6;
        sF7[ft] = f7;
    }

    // ---- scales 0-5 direct (each token loaded once) -------------------------
    unsigned hs = 0, h5 = 0;
    unsigned k0 = 0, k1 = 0, k2 = 0, k3 = 0, k4 = 0;
    int basei = 127 + tid;                 // stok index of token at t-1
#pragma unroll
    for (int i = 0; i < 32; i++) {
        unsigned tk = stok[basei - i];
        h5 ^= tk * C5(i);
        if (i < 16) {
            hs ^= tk * BASE(i);
            if (i == 0)  k0 = hs;
            if (i == 1)  k1 = hs;
            if (i == 3)  k2 = hs;
            if (i == 7)  k3 = hs;
            if (i == 15) k4 = hs;
        }
    }
    __syncthreads();

    // ---- scales 6/7 from block hashes --------------------------------------
    // position t = t0+tid -> ft_t = tid + HALO_F; h = XOR_j F(t - 8j)
    unsigned h6 = 0, h7 = 0;
#pragma unroll
    for (int j = 0; j < 16; j++) {
        h7 ^= sF7[tid + HALO_F - 8 * j];
        if (j < 8) h6 ^= sF6[tid + HALO_F - 8 * j];
    }

    k0 &= 0xFFFFu; k1 &= 0xFFFFu; k2 &= 0xFFFFu; k3 &= 0xFFFFu; k4 &= 0xFFFFu;
    unsigned k5 = h5 & 0xFFFFu, k6 = h6 & 0xFFFFu, k7 = h7 & 0xFFFFu;

    // ---- conditioning logits via precomputed projections --------------------
    float lg[8] = {0.f, 0.f, 0.f, 0.f, 0.f, 0.f, 0.f, 0.f};
    unsigned ks[4] = { k0, k1, k2, k3 };
#pragma unroll
    for (int s = 0; s < 4; s++) {
        const float4* p = ((const float4*)d_proj) + ((size_t)((s << 16) + ks[s])) * 2;
        float4 a = p[0], c = p[1];
        lg[0] += a.x; lg[1] += a.y; lg[2] += a.z; lg[3] += a.w;
        lg[4] += c.x; lg[5] += c.y; lg[6] += c.z; lg[7] += c.w;
    }
    unsigned cond = 0;
#pragma unroll
    for (int j = 0; j < 8; j++)
        if (lg[j] > 0.f) cond ^= BASE(j);
    cond &= 0xFFFFu;

    uint4 packed;
    packed.x = k0 | (k1 << 16);
    packed.y = k2 | (k3 << 16);
    packed.z = (k4 ^ cond) | ((k5 ^ cond) << 16);
    packed.w = (k6 ^ cond) | ((k7 ^ cond) << 16);
    ((uint4*)skey)[tid] = packed;
    __syncthreads();

    // ---- coalesced gather + store -------------------------------------------
    // Warp w, iteration iter -> position p = iter*16 + w.
    // Lane l: s = l>>2, q = l&3. Warp writes 512 contiguous bytes per iter.
    const float4* tab4 = (const float4*)tables;
    float4* out4 = (float4*)out;
    size_t obase = ((size_t)(rowbase + (unsigned)t0)) * 32;  // float4 units
    int lane = tid & 31;
    int w    = tid >> 5;                   // 16 warps
    int s    = lane >> 2;
    int q    = lane & 3;
#pragma unroll 8
    for (int iter = 0; iter < 32; iter++) {
        int p = (iter << 4) + w;
        unsigned key = skey[p * 8 + s];
        float4 v = tab4[((size_t)((s << 16) + key) << 2) + q];
        out4[obase + (size_t)p * 32 + lane] = v;
    }
}

extern "C" void kernel_launch(void* const* d_in, const int* in_sizes, int n_in,
                              void* d_out, int out_size)
{
    const unsigned* tokens = (const unsigned*)d_in[0];
    const float*    tables = (const float*)d_in[1];
    const float*    Wc     = (const float*)d_in[2];
    float*          out    = (float*)d_out;

    rhp_detect<<<1, 256>>>(tokens);
    rhp_proj<<<1024, 256>>>(tables, Wc);          // 4*65536 rows / 256
    rhp_main<<<256, 512>>>(tokens, tables, out);  // 32 rows * 8 chunks of 512
}

// round 12
// speedup vs baseline: 1.2166x; 1.1895x over previous
#include <cuda_runtime.h>
#include <stdint.h>

// ---------------------------------------------------------------------------
// RollingHashPyramid:
//   keys[s](b,t) = (XOR_{i<W_s} tokens[b,t-1-i] * P_s[i]) mod 65536
//   short  = tables[s][keys[s]], s=0..3  -> logits = concat(short) @ Wc^T
//   cond   = XOR of BASE[j] over j with logit_j > 0  (low 16 bits matter)
//   long   = tables[s][(keys[s]^cond) & 0xFFFF], s=4..7
//   out[b,t,s,:] = gathered rows.
// Scales 6/7 primes are periodic mod 8 -> factored 8-token block hashes.
// Logits: fp32 fast path; |logit| < 1e-5 falls back to a full double dot
// (sign-exact; fp32 abs error ~3e-9 << 1e-5 threshold).
// ---------------------------------------------------------------------------

__device__ __forceinline__ constexpr unsigned BASE(int i) {
    constexpr unsigned a[16] = {
        2654435761u, 2246822519u, 3266489917u, 2028178513u,
        1220703125u, 1610612741u,  805306457u,  402653189u,
        3674653429u, 2860486313u, 1073676287u, 2971215073u,
        1500450271u, 3267000013u, 2654435789u, 4049292737u };
    return a[i];
}
__device__ __forceinline__ constexpr unsigned EXTRA(int i) {
    constexpr unsigned a[16] = {
        2246822531u, 3266489927u, 2028178519u, 1220703133u,
        1610612759u,  805306463u,  402653201u, 3674653441u,
        2860486319u, 1073676311u, 2971215091u, 1500450277u,
        3267000023u, 2654435801u, 4049292751u, 2246822537u };
    return a[i];
}
__device__ __forceinline__ constexpr unsigned C5(int i) {
    return ((i < 16) ? BASE(i) : EXTRA(i - 16)) ^ 3735928559u;  // ^0xDEADBEEF
}
__device__ __forceinline__ constexpr unsigned C6(int k) {
    return BASE(k) ^ 3405691582u;  // ^0xCAFEBABE
}
__device__ __forceinline__ constexpr unsigned C7(int k) {
    return BASE(k) ^ 2343432205u;  // ^0x8BADF00D
}

// Scratch: proj[s][bucket][j] = sum_e tables[s][bucket][e] * Wc[j][s*16+e]
__device__ float d_proj[4 * 65536 * 8];   // 8 MB
__device__ unsigned d_tok_stride;          // 2 if tokens are int64, 1 if int32

// ---------------------------------------------------------------------------
// Kernel 1: project the 4 short tables through Wc once per bucket (fp32).
// Block 0 also detects token element width (int64 high words all zero).
// ---------------------------------------------------------------------------
__global__ __launch_bounds__(256) void rhp_proj(
    const float* __restrict__ tables, const float* __restrict__ Wc,
    const unsigned* __restrict__ tok)
{
    __shared__ float swc[512];  // Wc[8][64]
    int tid = threadIdx.x;
    if (tid < 128) ((float4*)swc)[tid] = ((const float4*)Wc)[tid];

    unsigned any = 0;
    if (blockIdx.x == 0) {
        any = tok[2 * tid + 1] | tok[2 * (tid + 256) + 1] |
              tok[2 * (tid + 512) + 1] | tok[2 * (tid + 768) + 1];
    }
    int blk = __syncthreads_or(any != 0);   // barrier + OR (all blocks)
    if (blockIdx.x == 0 && tid == 0) d_tok_stride = blk ? 1u : 2u;

    int row = blockIdx.x * 256 + tid;      // row = s*65536 + bucket, s in 0..3
    int s = row >> 16;
    const float4* t4 = (const float4*)tables + (size_t)row * 4;
    float4 r0 = t4[0], r1 = t4[1], r2 = t4[2], r3 = t4[3];
    float r[16] = { r0.x, r0.y, r0.z, r0.w, r1.x, r1.y, r1.z, r1.w,
                    r2.x, r2.y, r2.z, r2.w, r3.x, r3.y, r3.z, r3.w };

    float o[8];
#pragma unroll
    for (int j = 0; j < 8; j++) {
        const float* w = &swc[j * 64 + s * 16];
        float acc = 0.f;
#pragma unroll
        for (int e = 0; e < 16; e++)
            acc = fmaf(r[e], w[e], acc);
        o[j] = acc;
    }
    float4* p = ((float4*)d_proj) + (size_t)row * 2;
    p[0] = make_float4(o[0], o[1], o[2], o[3]);
    p[1] = make_float4(o[4], o[5], o[6], o[7]);
}

// ---------------------------------------------------------------------------
// Kernel 2: main. 512 positions per block, one thread per position.
// Scales 0-5 direct (48 IMAD); 6/7 via shared block hashes. Logits from
// d_proj (fp32) with rare double-exact fallback. Warp-remapped coalesced
// gather + store.
// ---------------------------------------------------------------------------
#define POS 512
#define HALO_F 120          // F7 needed down to t-120
__global__ __launch_bounds__(POS) void rhp_main(
    const unsigned* __restrict__ tok,      // raw int32 view of token buffer
    const float* __restrict__ tables,
    const float* __restrict__ Wc,
    float* __restrict__ out)
{
    __shared__ unsigned stok[POS + 128];           // tokens [t0-128, t0+POS)
    __shared__ unsigned sF6[POS + HALO_F];
    __shared__ unsigned sF7[POS + HALO_F];
    __shared__ unsigned short skey[POS * 8];
    __shared__ float swc[512];                     // Wc for fallback

    int tid = threadIdx.x;
    int b   = blockIdx.x >> 3;             // 32 rows
    int t0  = (blockIdx.x & 7) << 9;       // 8 chunks of 512
    unsigned rowbase = (unsigned)b * 4096u;
    unsigned stride = d_tok_stride;        // 1 (int32) or 2 (int64)

    if (tid < 128) ((float4*)swc)[tid] = ((const float4*)Wc)[tid];

    // ---- token staging ------------------------------------------------------
    for (int i = tid; i < POS + 128; i += POS) {
        int t = t0 - 128 + i;
        unsigned v = 0;
        if (t >= 0) v = tok[stride * (rowbase + (unsigned)t)];
        stok[i] = v;
    }
    __syncthreads();

    // ---- F6/F7 block hashes: F(t) = XOR_{r<8} tok(t-1-r)*C(r) ---------------
    for (int ft = tid; ft < POS + HALO_F; ft += POS) {
        unsigned f6 = 0, f7 = 0;
#pragma unroll
        for (int q = 0; q < 8; q++) {
            unsigned tk = stok[ft + q];    // token at t-1-r with r = 7-q
            f6 ^= tk * C6(7 - q);
            f7 ^= tk * C7(7 - q);
        }
        sF6[ft] = f6;
        sF7[ft] = f7;
    }

    // ---- scales 0-5 direct --------------------------------------------------
    unsigned hs = 0, h5 = 0;
    unsigned k0 = 0, k1 = 0, k2 = 0, k3 = 0, k4 = 0;
    int basei = 127 + tid;                 // stok index of token at t-1
#pragma unroll
    for (int i = 0; i < 32; i++) {
        unsigned tk = stok[basei - i];
        h5 ^= tk * C5(i);
        if (i < 16) {
            hs ^= tk * BASE(i);
            if (i == 0)  k0 = hs;
            if (i == 1)  k1 = hs;
            if (i == 3)  k2 = hs;
            if (i == 7)  k3 = hs;
            if (i == 15) k4 = hs;
        }
    }
    __syncthreads();

    // ---- scales 6/7 from block hashes ---------------------------------------
    unsigned h6 = 0, h7 = 0;
#pragma unroll
    for (int j = 0; j < 16; j++) {
        h7 ^= sF7[tid + HALO_F - 8 * j];
        if (j < 8) h6 ^= sF6[tid + HALO_F - 8 * j];
    }

    k0 &= 0xFFFFu; k1 &= 0xFFFFu; k2 &= 0xFFFFu; k3 &= 0xFFFFu; k4 &= 0xFFFFu;
    unsigned k5 = h5 & 0xFFFFu, k6 = h6 & 0xFFFFu, k7 = h7 & 0xFFFFu;

    // ---- conditioning logits ------------------------------------------------
    float lg[8] = {0.f, 0.f, 0.f, 0.f, 0.f, 0.f, 0.f, 0.f};
    unsigned ks[4] = { k0, k1, k2, k3 };
#pragma unroll
    for (int s = 0; s < 4; s++) {
        const float4* p = ((const float4*)d_proj) + ((size_t)((s << 16) + ks[s])) * 2;
        float4 a = p[0], c = p[1];
        lg[0] += a.x; lg[1] += a.y; lg[2] += a.z; lg[3] += a.w;
        lg[4] += c.x; lg[5] += c.y; lg[6] += c.z; lg[7] += c.w;
    }
    // rare sign-critical fallback: exact double dot over the 64 inputs
#pragma unroll
    for (int j = 0; j < 8; j++) {
        if (fabsf(lg[j]) < 1e-5f) {
            double acc = 0.0;
#pragma unroll
            for (int s = 0; s < 4; s++) {
                const float* row = tables + ((size_t)((s << 16) + ks[s])) * 16;
                const float* w = &swc[j * 64 + s * 16];
#pragma unroll
                for (int e = 0; e < 16; e++)
                    acc += (double)row[e] * (double)w[e];
            }
            lg[j] = (float)acc;
        }
    }
    unsigned cond = 0;
#pragma unroll
    for (int j = 0; j < 8; j++)
        if (lg[j] > 0.f) cond ^= BASE(j);
    cond &= 0xFFFFu;

    uint4 packed;
    packed.x = k0 | (k1 << 16);
    packed.y = k2 | (k3 << 16);
    packed.z = (k4 ^ cond) | ((k5 ^ cond) << 16);
    packed.w = (k6 ^ cond) | ((k7 ^ cond) << 16);
    ((uint4*)skey)[tid] = packed;
    __syncthreads();

    // ---- coalesced gather + store -------------------------------------------
    // Warp w, iteration iter -> position p = iter*16 + w.
    // Lane l: s = l>>2, q = l&3. Warp writes 512 contiguous bytes per iter.
    const float4* tab4 = (const float4*)tables;
    float4* out4 = (float4*)out;
    size_t obase = ((size_t)(rowbase + (unsigned)t0)) * 32;  // float4 units
    int lane = tid & 31;
    int w    = tid >> 5;                   // 16 warps
    int s    = lane >> 2;
    int q    = lane & 3;
#pragma unroll 8
    for (int iter = 0; iter < 32; iter++) {
        int p = (iter << 4) + w;
        unsigned key = skey[p * 8 + s];
        float4 v = tab4[((size_t)((s << 16) + key) << 2) + q];
        out4[obase + (size_t)p * 32 + lane] = v;
    }
}

extern "C" void kernel_launch(void* const* d_in, const int* in_sizes, int n_in,
                              void* d_out, int out_size)
{
    const unsigned* tokens = (const unsigned*)d_in[0];
    const float*    tables = (const float*)d_in[1];
    const float*    Wc     = (const float*)d_in[2];
    float*          out    = (float*)d_out;

    rhp_proj<<<1024, 256>>>(tables, Wc, tokens);      // 4*65536 rows / 256
    rhp_main<<<256, 512>>>(tokens, tables, Wc, out);  // 32 rows * 8 chunks
}

// round 13
// speedup vs baseline: 1.7416x; 1.4315x over previous
#include <cuda_runtime.h>
#include <stdint.h>

// ---------------------------------------------------------------------------
// RollingHashPyramid — three-kernel pipeline:
//   K1 rhp_proj:   proj[s][bucket][j] = tables[s][bucket] . Wc[j, s*16:]  (fp32)
//                  (+ token element-width detection in block 0)
//   K2 rhp_keys:   per-position hash keys (scales 0-7) + conditioning XOR,
//                  packed 8 x u16 per position -> d_keys (2 MB)
//   K3 rhp_gather: one warp per position; 8 table rows gathered and stored
//                  contiguously (512 B per position).
// Scales 6/7 primes are periodic mod 8 -> factored 8-token block hashes.
// Logits: fp32 fast path; |logit| < 1e-5 -> exact double recompute.
// ---------------------------------------------------------------------------

__device__ __forceinline__ constexpr unsigned BASE(int i) {
    constexpr unsigned a[16] = {
        2654435761u, 2246822519u, 3266489917u, 2028178513u,
        1220703125u, 1610612741u,  805306457u,  402653189u,
        3674653429u, 2860486313u, 1073676287u, 2971215073u,
        1500450271u, 3267000013u, 2654435789u, 4049292737u };
    return a[i];
}
__device__ __forceinline__ constexpr unsigned EXTRA(int i) {
    constexpr unsigned a[16] = {
        2246822531u, 3266489927u, 2028178519u, 1220703133u,
        1610612759u,  805306463u,  402653201u, 3674653441u,
        2860486319u, 1073676311u, 2971215091u, 1500450277u,
        3267000023u, 2654435801u, 4049292751u, 2246822537u };
    return a[i];
}
__device__ __forceinline__ constexpr unsigned C5(int i) {
    return ((i < 16) ? BASE(i) : EXTRA(i - 16)) ^ 3735928559u;  // ^0xDEADBEEF
}
__device__ __forceinline__ constexpr unsigned C6(int k) {
    return BASE(k) ^ 3405691582u;  // ^0xCAFEBABE
}
__device__ __forceinline__ constexpr unsigned C7(int k) {
    return BASE(k) ^ 2343432205u;  // ^0x8BADF00D
}

__device__ float d_proj[4 * 65536 * 8];   // 8 MB projection scratch
__device__ uint4 d_keys[32 * 4096];        // 2 MB packed keys (8 x u16 / pos)
__device__ unsigned d_tok_stride;          // 2 if tokens are int64, 1 if int32

// ---------------------------------------------------------------------------
// K1: projection (fp32) + width detection.
// ---------------------------------------------------------------------------
__global__ __launch_bounds__(256) void rhp_proj(
    const float* __restrict__ tables, const float* __restrict__ Wc,
    const unsigned* __restrict__ tok)
{
    __shared__ float swc[512];  // Wc[8][64]
    int tid = threadIdx.x;
    if (tid < 128) ((float4*)swc)[tid] = ((const float4*)Wc)[tid];

    unsigned any = 0;
    if (blockIdx.x == 0) {
        any = tok[2 * tid + 1] | tok[2 * (tid + 256) + 1] |
              tok[2 * (tid + 512) + 1] | tok[2 * (tid + 768) + 1];
    }
    int blk = __syncthreads_or(any != 0);   // barrier + OR (all blocks)
    if (blockIdx.x == 0 && tid == 0) d_tok_stride = blk ? 1u : 2u;

    int row = blockIdx.x * 256 + tid;      // row = s*65536 + bucket, s in 0..3
    int s = row >> 16;
    const float4* t4 = (const float4*)tables + (size_t)row * 4;
    float4 r0 = t4[0], r1 = t4[1], r2 = t4[2], r3 = t4[3];
    float r[16] = { r0.x, r0.y, r0.z, r0.w, r1.x, r1.y, r1.z, r1.w,
                    r2.x, r2.y, r2.z, r2.w, r3.x, r3.y, r3.z, r3.w };

    float o[8];
#pragma unroll
    for (int j = 0; j < 8; j++) {
        const float* w = &swc[j * 64 + s * 16];
        float acc = 0.f;
#pragma unroll
        for (int e = 0; e < 16; e++)
            acc = fmaf(r[e], w[e], acc);
        o[j] = acc;
    }
    float4* p = ((float4*)d_proj) + (size_t)row * 2;
    p[0] = make_float4(o[0], o[1], o[2], o[3]);
    p[1] = make_float4(o[4], o[5], o[6], o[7]);
}

// ---------------------------------------------------------------------------
// K2: keys. 512 positions per block, one thread per position; writes the
// packed 8 x u16 keys (coalesced 16 B/thread).
// ---------------------------------------------------------------------------
#define POS 512
#define HALO_F 120          // F7 needed down to t-120
__global__ __launch_bounds__(POS) void rhp_keys(
    const unsigned* __restrict__ tok,      // raw int32 view of token buffer
    const float* __restrict__ tables,
    const float* __restrict__ Wc)
{
    __shared__ unsigned stok[POS + 128];           // tokens [t0-128, t0+POS)
    __shared__ unsigned sF6[POS + HALO_F];
    __shared__ unsigned sF7[POS + HALO_F];
    __shared__ float swc[512];                     // Wc for fallback

    int tid = threadIdx.x;
    int b   = blockIdx.x >> 3;             // 32 rows
    int t0  = (blockIdx.x & 7) << 9;       // 8 chunks of 512
    unsigned rowbase = (unsigned)b * 4096u;
    unsigned stride = d_tok_stride;        // 1 (int32) or 2 (int64)

    if (tid < 128) ((float4*)swc)[tid] = ((const float4*)Wc)[tid];

    for (int i = tid; i < POS + 128; i += POS) {
        int t = t0 - 128 + i;
        unsigned v = 0;
        if (t >= 0) v = tok[stride * (rowbase + (unsigned)t)];
        stok[i] = v;
    }
    __syncthreads();

    // F6/F7 block hashes: F(t) = XOR_{r<8} tok(t-1-r)*C(r)
    for (int ft = tid; ft < POS + HALO_F; ft += POS) {
        unsigned f6 = 0, f7 = 0;
#pragma unroll
        for (int q = 0; q < 8; q++) {
            unsigned tk = stok[ft + q];    // token at t-1-r with r = 7-q
            f6 ^= tk * C6(7 - q);
            f7 ^= tk * C7(7 - q);
        }
        sF6[ft] = f6;
        sF7[ft] = f7;
    }

    // scales 0-5 direct
    unsigned hs = 0, h5 = 0;
    unsigned k0 = 0, k1 = 0, k2 = 0, k3 = 0, k4 = 0;
    int basei = 127 + tid;                 // stok index of token at t-1
#pragma unroll
    for (int i = 0; i < 32; i++) {
        unsigned tk = stok[basei - i];
        h5 ^= tk * C5(i);
        if (i < 16) {
            hs ^= tk * BASE(i);
            if (i == 0)  k0 = hs;
            if (i == 1)  k1 = hs;
            if (i == 3)  k2 = hs;
            if (i == 7)  k3 = hs;
            if (i == 15) k4 = hs;
        }
    }
    __syncthreads();

    // scales 6/7 from block hashes
    unsigned h6 = 0, h7 = 0;
#pragma unroll
    for (int j = 0; j < 16; j++) {
        h7 ^= sF7[tid + HALO_F - 8 * j];
        if (j < 8) h6 ^= sF6[tid + HALO_F - 8 * j];
    }

    k0 &= 0xFFFFu; k1 &= 0xFFFFu; k2 &= 0xFFFFu; k3 &= 0xFFFFu; k4 &= 0xFFFFu;
    unsigned k5 = h5 & 0xFFFFu, k6 = h6 & 0xFFFFu, k7 = h7 & 0xFFFFu;

    // conditioning logits (fp32 via d_proj, rare exact fallback)
    float lg[8] = {0.f, 0.f, 0.f, 0.f, 0.f, 0.f, 0.f, 0.f};
    unsigned ks[4] = { k0, k1, k2, k3 };
#pragma unroll
    for (int s = 0; s < 4; s++) {
        const float4* p = ((const float4*)d_proj) + ((size_t)((s << 16) + ks[s])) * 2;
        float4 a = p[0], c = p[1];
        lg[0] += a.x; lg[1] += a.y; lg[2] += a.z; lg[3] += a.w;
        lg[4] += c.x; lg[5] += c.y; lg[6] += c.z; lg[7] += c.w;
    }
#pragma unroll
    for (int j = 0; j < 8; j++) {
        if (fabsf(lg[j]) < 1e-5f) {
            double acc = 0.0;
#pragma unroll
            for (int s = 0; s < 4; s++) {
                const float* row = tables + ((size_t)((s << 16) + ks[s])) * 16;
                const float* w = &swc[j * 64 + s * 16];
#pragma unroll
                for (int e = 0; e < 16; e++)
                    acc += (double)row[e] * (double)w[e];
            }
            lg[j] = (float)acc;
        }
    }
    unsigned cond = 0;
#pragma unroll
    for (int j = 0; j < 8; j++)
        if (lg[j] > 0.f) cond ^= BASE(j);
    cond &= 0xFFFFu;

    uint4 packed;
    packed.x = k0 | (k1 << 16);
    packed.y = k2 | (k3 << 16);
    packed.z = (k4 ^ cond) | ((k5 ^ cond) << 16);
    packed.w = (k6 ^ cond) | ((k7 ^ cond) << 16);
    d_keys[rowbase + (unsigned)t0 + (unsigned)tid] = packed;
}

// ---------------------------------------------------------------------------
// K3: gather. One warp per position; lane l -> scale s = l>>2, quarter
// q = l&3. Uniform 16 B key load per warp, LDG.128 gather, STG.128 store
// (512 contiguous bytes per warp). 131072 warps -> full-chip TLP.
// ---------------------------------------------------------------------------
__global__ __launch_bounds__(256) void rhp_gather(
    const float* __restrict__ tables, float* __restrict__ out)
{
    int p    = (blockIdx.x << 3) + (threadIdx.x >> 5);   // global position
    int lane = threadIdx.x & 31;
    int s    = lane >> 2;
    int q    = lane & 3;

    uint4 pk = d_keys[p];
    unsigned comp = (s < 2) ? ((s & 1) ? pk.y : pk.x)    // s>>1 == 0 -> x ... wait
                            : ((s & 1) ? pk.w : pk.z);
    // component mapping: s=0,1 -> x; 2,3 -> y; 4,5 -> z; 6,7 -> w
    unsigned c2 = (s >> 1 == 0) ? pk.x : (s >> 1 == 1) ? pk.y : (s >> 1 == 2) ? pk.z : pk.w;
    unsigned key = (c2 >> ((s & 1) << 4)) & 0xFFFFu;
    (void)comp;

    const float4* tab4 = (const float4*)tables;
    float4 v = tab4[((size_t)((s << 16) + key) << 2) + q];
    ((float4*)out)[(size_t)p * 32 + lane] = v;
}

extern "C" void kernel_launch(void* const* d_in, const int* in_sizes, int n_in,
                              void* d_out, int out_size)
{
    const unsigned* tokens = (const unsigned*)d_in[0];
    const float*    tables = (const float*)d_in[1];
    const float*    Wc     = (const float*)d_in[2];
    float*          out    = (float*)d_out;

    rhp_proj<<<1024, 256>>>(tables, Wc, tokens);   // 4*65536 rows / 256
    rhp_keys<<<256, 512>>>(tokens, tables, Wc);    // 32 rows * 8 chunks
    rhp_gather<<<16384, 256>>>(tables, out);       // 131072 positions, 8 warps/blk
}

// round 14
// speedup vs baseline: 1.8309x; 1.0513x over previous
#include <cuda_runtime.h>
#include <stdint.h>

// ---------------------------------------------------------------------------
// RollingHashPyramid — three-kernel pipeline:
//   K1 rhp_proj:   proj[s][bucket][j] = tables[s][bucket] . Wc[j, s*16:]  (fp32)
//   K2 rhp_keys:   per-position hash keys (scales 0-7) + conditioning XOR,
//                  packed 8 x u16 per position -> d_keys (2 MB)
//                  (per-block token element-width detection, inline)
//   K3 rhp_gather: one warp per position; 8 table rows gathered and stored
//                  contiguously (512 B per position).
// Scales 6/7 primes are periodic mod 8 -> factored 8-token block hashes.
// Logits: fp32 fast path; |logit| < 1e-5 -> exact double recompute.
// ---------------------------------------------------------------------------

__device__ __forceinline__ constexpr unsigned BASE(int i) {
    constexpr unsigned a[16] = {
        2654435761u, 2246822519u, 3266489917u, 2028178513u,
        1220703125u, 1610612741u,  805306457u,  402653189u,
        3674653429u, 2860486313u, 1073676287u, 2971215073u,
        1500450271u, 3267000013u, 2654435789u, 4049292737u };
    return a[i];
}
__device__ __forceinline__ constexpr unsigned EXTRA(int i) {
    constexpr unsigned a[16] = {
        2246822531u, 3266489927u, 2028178519u, 1220703133u,
        1610612759u,  805306463u,  402653201u, 3674653441u,
        2860486319u, 1073676311u, 2971215091u, 1500450277u,
        3267000023u, 2654435801u, 4049292751u, 2246822537u };
    return a[i];
}
__device__ __forceinline__ constexpr unsigned C5(int i) {
    return ((i < 16) ? BASE(i) : EXTRA(i - 16)) ^ 3735928559u;  // ^0xDEADBEEF
}
__device__ __forceinline__ constexpr unsigned C6(int k) {
    return BASE(k) ^ 3405691582u;  // ^0xCAFEBABE
}
__device__ __forceinline__ constexpr unsigned C7(int k) {
    return BASE(k) ^ 2343432205u;  // ^0x8BADF00D
}

__device__ float d_proj[4 * 65536 * 8];   // 8 MB projection scratch
__device__ uint4 d_keys[32 * 4096];        // 2 MB packed keys (8 x u16 / pos)

// ---------------------------------------------------------------------------
// K1: projection (fp32).
// ---------------------------------------------------------------------------
__global__ __launch_bounds__(256) void rhp_proj(
    const float* __restrict__ tables, const float* __restrict__ Wc)
{
    __shared__ float swc[512];  // Wc[8][64]
    int tid = threadIdx.x;
    if (tid < 128) ((float4*)swc)[tid] = ((const float4*)Wc)[tid];
    __syncthreads();

    int row = blockIdx.x * 256 + tid;      // row = s*65536 + bucket, s in 0..3
    int s = row >> 16;
    const float4* t4 = (const float4*)tables + (size_t)row * 4;
    float4 r0 = t4[0], r1 = t4[1], r2 = t4[2], r3 = t4[3];
    float r[16] = { r0.x, r0.y, r0.z, r0.w, r1.x, r1.y, r1.z, r1.w,
                    r2.x, r2.y, r2.z, r2.w, r3.x, r3.y, r3.z, r3.w };

    float o[8];
#pragma unroll
    for (int j = 0; j < 8; j++) {
        const float* w = &swc[j * 64 + s * 16];
        float acc = 0.f;
#pragma unroll
        for (int e = 0; e < 16; e++)
            acc = fmaf(r[e], w[e], acc);
        o[j] = acc;
    }
    float4* p = ((float4*)d_proj) + (size_t)row * 2;
    p[0] = make_float4(o[0], o[1], o[2], o[3]);
    p[1] = make_float4(o[4], o[5], o[6], o[7]);
}

// ---------------------------------------------------------------------------
// K2: keys. 128 positions per block (1024 blocks -> ~7 blocks/SM of TLP),
// one thread per position; writes packed 8 x u16 keys (16 B/thread).
// ---------------------------------------------------------------------------
#define POS 128
#define HALO_F 120          // F7 needed down to t-120
__global__ __launch_bounds__(POS) void rhp_keys(
    const unsigned* __restrict__ tok,      // raw int32 view of token buffer
    const float* __restrict__ tables,
    const float* __restrict__ Wc)
{
    __shared__ unsigned stok[POS + 128];           // tokens [t0-128, t0+POS)
    __shared__ unsigned sF6[POS + HALO_F];
    __shared__ unsigned sF7[POS + HALO_F];
    __shared__ float swc[512];                     // Wc for fallback

    int tid = threadIdx.x;
    int b   = blockIdx.x >> 5;             // 32 rows
    int t0  = (blockIdx.x & 31) << 7;      // 32 chunks of 128
    unsigned rowbase = (unsigned)b * 4096u;

    ((float4*)swc)[tid] = ((const float4*)Wc)[tid];  // 128 float4 = Wc[8][64]

    // ---- inline token-width detection (self-contained per block) ----------
    // int64 tokens (<1024): odd int32 words are zero high-halves.
    // int32 tokens: words 1..511 are random in [0,1024): P(all 0) ~ 1024^-256.
    unsigned any = tok[2 * tid + 1] | tok[2 * (tid + POS) + 1];
    unsigned stride = __syncthreads_or(any != 0) ? 1u : 2u;

    // ---- token staging ------------------------------------------------------
#pragma unroll
    for (int i = tid; i < POS + 128; i += POS) {
        int t = t0 - 128 + i;
        unsigned v = 0;
        if (t >= 0) v = tok[stride * (rowbase + (unsigned)t)];
        stok[i] = v;
    }
    __syncthreads();

    // ---- F6/F7 block hashes: F(t) = XOR_{r<8} tok(t-1-r)*C(r) ---------------
#pragma unroll
    for (int ft = tid; ft < POS + HALO_F; ft += POS) {
        unsigned f6 = 0, f7 = 0;
#pragma unroll
        for (int q = 0; q < 8; q++) {
            unsigned tk = stok[ft + q];    // token at t-1-r with r = 7-q
            f6 ^= tk * C6(7 - q);
            f7 ^= tk * C7(7 - q);
        }
        sF6[ft] = f6;
        sF7[ft] = f7;
    }

    // ---- scales 0-5 direct --------------------------------------------------
    unsigned hs = 0, h5 = 0;
    unsigned k0 = 0, k1 = 0, k2 = 0, k3 = 0, k4 = 0;
    int basei = 127 + tid;                 // stok index of token at t-1
#pragma unroll
    for (int i = 0; i < 32; i++) {
        unsigned tk = stok[basei - i];
        h5 ^= tk * C5(i);
        if (i < 16) {
            hs ^= tk * BASE(i);
            if (i == 0)  k0 = hs;
            if (i == 1)  k1 = hs;
            if (i == 3)  k2 = hs;
            if (i == 7)  k3 = hs;
            if (i == 15) k4 = hs;
        }
    }
    __syncthreads();

    // ---- scales 6/7 from block hashes ---------------------------------------
    unsigned h6 = 0, h7 = 0;
#pragma unroll
    for (int j = 0; j < 16; j++) {
        h7 ^= sF7[tid + HALO_F - 8 * j];
        if (j < 8) h6 ^= sF6[tid + HALO_F - 8 * j];
    }

    k0 &= 0xFFFFu; k1 &= 0xFFFFu; k2 &= 0xFFFFu; k3 &= 0xFFFFu; k4 &= 0xFFFFu;
    unsigned k5 = h5 & 0xFFFFu, k6 = h6 & 0xFFFFu, k7 = h7 & 0xFFFFu;

    // ---- conditioning logits (fp32 via d_proj, rare exact fallback) ---------
    float lg[8] = {0.f, 0.f, 0.f, 0.f, 0.f, 0.f, 0.f, 0.f};
    unsigned ks[4] = { k0, k1, k2, k3 };
#pragma unroll
    for (int s = 0; s < 4; s++) {
        const float4* p = ((const float4*)d_proj) + ((size_t)((s << 16) + ks[s])) * 2;
        float4 a = p[0], c = p[1];
        lg[0] += a.x; lg[1] += a.y; lg[2] += a.z; lg[3] += a.w;
        lg[4] += c.x; lg[5] += c.y; lg[6] += c.z; lg[7] += c.w;
    }
#pragma unroll
    for (int j = 0; j < 8; j++) {
        if (fabsf(lg[j]) < 1e-5f) {
            double acc = 0.0;
#pragma unroll
            for (int s = 0; s < 4; s++) {
                const float* row = tables + ((size_t)((s << 16) + ks[s])) * 16;
                const float* w = &swc[j * 64 + s * 16];
#pragma unroll
                for (int e = 0; e < 16; e++)
                    acc += (double)row[e] * (double)w[e];
            }
            lg[j] = (float)acc;
        }
    }
    unsigned cond = 0;
#pragma unroll
    for (int j = 0; j < 8; j++)
        if (lg[j] > 0.f) cond ^= BASE(j);
    cond &= 0xFFFFu;

    uint4 packed;
    packed.x = k0 | (k1 << 16);
    packed.y = k2 | (k3 << 16);
    packed.z = (k4 ^ cond) | ((k5 ^ cond) << 16);
    packed.w = (k6 ^ cond) | ((k7 ^ cond) << 16);
    d_keys[rowbase + (unsigned)t0 + (unsigned)tid] = packed;
}

// ---------------------------------------------------------------------------
// K3: gather. One warp per position; lane l -> scale s = l>>2, quarter
// q = l&3. Uniform 16 B key load per warp (broadcast), LDG.128 gather,
// STG.128 store (512 contiguous bytes per warp). 131072 warps of TLP.
// ---------------------------------------------------------------------------
__global__ __launch_bounds__(256) void rhp_gather(
    const float* __restrict__ tables, float* __restrict__ out)
{
    int p    = (blockIdx.x << 3) + (threadIdx.x >> 5);   // global position
    int lane = threadIdx.x & 31;
    int s    = lane >> 2;
    int q    = lane & 3;

    uint4 pk = d_keys[p];
    unsigned c2 = (s < 2) ? pk.x : (s < 4) ? pk.y : (s < 6) ? pk.z : pk.w;
    unsigned key = (s & 1) ? (c2 >> 16) : (c2 & 0xFFFFu);

    const float4* tab4 = (const float4*)tables;
    float4 v = tab4[((size_t)((s << 16) + key) << 2) + q];
    ((float4*)out)[(size_t)p * 32 + lane] = v;
}

extern "C" void kernel_launch(void* const* d_in, const int* in_sizes, int n_in,
                              void* d_out, int out_size)
{
    const unsigned* tokens = (const unsigned*)d_in[0];
    const float*    tables = (const float*)d_in[1];
    const float*    Wc     = (const float*)d_in[2];
    float*          out    = (float*)d_out;

    rhp_proj<<<1024, 256>>>(tables, Wc);           // 4*65536 rows / 256
    rhp_keys<<<1024, 128>>>(tokens, tables, Wc);   // 32 rows * 32 chunks of 128
    rhp_gather<<<16384, 256>>>(tables, out);       // 131072 positions
}

// round 17
// speedup vs baseline: 1.8919x; 1.0333x over previous
#include <cuda_runtime.h>
#include <stdint.h>

// ---------------------------------------------------------------------------
// RollingHashPyramid — three-kernel pipeline:
//   K1 rhp_proj:   proj[s][bucket][j] = tables[s][bucket] . Wc[j, s*16:]  (fp32)
//   K2 rhp_keys:   per-position hash keys (scales 0-7) + conditioning XOR,
//                  packed 8 x u16 per position -> d_keys (2 MB)
//   K3 rhp_gather: one warp per position; 8 table rows gathered and stored
//                  contiguously (512 B per position).
// Cache policy: tables/proj reads use createpolicy L2::evict_last cache-hint
// (pin the 40 MB working set in the 126 MB L2); the 64 MB output stream is
// st.global.cs (evict-first) so it cannot thrash the pinned tables.
// Scales 6/7 primes are periodic mod 8 -> factored 8-token block hashes.
// Logits: fp32 fast path; |logit| < 1e-5 -> exact double recompute.
// ---------------------------------------------------------------------------

__device__ __forceinline__ constexpr unsigned BASE(int i) {
    constexpr unsigned a[16] = {
        2654435761u, 2246822519u, 3266489917u, 2028178513u,
        1220703125u, 1610612741u,  805306457u,  402653189u,
        3674653429u, 2860486313u, 1073676287u, 2971215073u,
        1500450271u, 3267000013u, 2654435789u, 4049292737u };
    return a[i];
}
__device__ __forceinline__ constexpr unsigned EXTRA(int i) {
    constexpr unsigned a[16] = {
        2246822531u, 3266489927u, 2028178519u, 1220703133u,
        1610612759u,  805306463u,  402653201u, 3674653441u,
        2860486319u, 1073676311u, 2971215091u, 1500450277u,
        3267000023u, 2654435801u, 4049292751u, 2246822537u };
    return a[i];
}
__device__ __forceinline__ constexpr unsigned C5(int i) {
    return ((i < 16) ? BASE(i) : EXTRA(i - 16)) ^ 3735928559u;  // ^0xDEADBEEF
}
__device__ __forceinline__ constexpr unsigned C6(int k) {
    return BASE(k) ^ 3405691582u;  // ^0xCAFEBABE
}
__device__ __forceinline__ constexpr unsigned C7(int k) {
    return BASE(k) ^ 2343432205u;  // ^0x8BADF00D
}

// ---- cache-policy memory ops ------------------------------------------------
__device__ __forceinline__ uint64_t mk_pin_policy() {
    uint64_t pol;
    asm("createpolicy.fractional.L2::evict_last.b64 %0, 1.0;" : "=l"(pol));
    return pol;
}
__device__ __forceinline__ float4 ldg_pin(const float4* p, uint64_t pol) {
    float4 v;
    asm volatile("ld.global.nc.L2::cache_hint.v4.f32 {%0,%1,%2,%3}, [%4], %5;"
                 : "=f"(v.x), "=f"(v.y), "=f"(v.z), "=f"(v.w)
                 : "l"(p), "l"(pol));
    return v;
}
__device__ __forceinline__ void stg_stream(float4* p, float4 v) {  // evict-first
    asm volatile("st.global.cs.v4.f32 [%0], {%1,%2,%3,%4};"
                 :: "l"(p), "f"(v.x), "f"(v.y), "f"(v.z), "f"(v.w) : "memory");
}

__device__ float d_proj[4 * 65536 * 8];   // 8 MB projection scratch
__device__ uint4 d_keys[32 * 4096];        // 2 MB packed keys (8 x u16 / pos)

// ---------------------------------------------------------------------------
// K1: projection (fp32). Table reads pinned (primes L2 for the short tables).
// ---------------------------------------------------------------------------
__global__ __launch_bounds__(256) void rhp_proj(
    const float* __restrict__ tables, const float* __restrict__ Wc)
{
    __shared__ float swc[512];  // Wc[8][64]
    int tid = threadIdx.x;
    if (tid < 128) ((float4*)swc)[tid] = ((const float4*)Wc)[tid];
    __syncthreads();

    uint64_t pol = mk_pin_policy();
    int row = blockIdx.x * 256 + tid;      // row = s*65536 + bucket, s in 0..3
    int s = row >> 16;
    const float4* t4 = (const float4*)tables + (size_t)row * 4;
    float4 r0 = ldg_pin(t4 + 0, pol), r1 = ldg_pin(t4 + 1, pol);
    float4 r2 = ldg_pin(t4 + 2, pol), r3 = ldg_pin(t4 + 3, pol);
    float r[16] = { r0.x, r0.y, r0.z, r0.w, r1.x, r1.y, r1.z, r1.w,
                    r2.x, r2.y, r2.z, r2.w, r3.x, r3.y, r3.z, r3.w };

    float o[8];
#pragma unroll
    for (int j = 0; j < 8; j++) {
        const float* w = &swc[j * 64 + s * 16];
        float acc = 0.f;
#pragma unroll
        for (int e = 0; e < 16; e++)
            acc = fmaf(r[e], w[e], acc);
        o[j] = acc;
    }
    float4* p = ((float4*)d_proj) + (size_t)row * 2;
    p[0] = make_float4(o[0], o[1], o[2], o[3]);
    p[1] = make_float4(o[4], o[5], o[6], o[7]);
}

// ---------------------------------------------------------------------------
// K2: keys. 128 positions per block (1024 blocks), one thread per position;
// writes packed 8 x u16 keys (16 B/thread).
// ---------------------------------------------------------------------------
#define POS 128
#define HALO_F 120          // F7 needed down to t-120
__global__ __launch_bounds__(POS) void rhp_keys(
    const unsigned* __restrict__ tok,      // raw int32 view of token buffer
    const float* __restrict__ tables,
    const float* __restrict__ Wc)
{
    __shared__ unsigned stok[POS + 128];           // tokens [t0-128, t0+POS)
    __shared__ unsigned sF6[POS + HALO_F];
    __shared__ unsigned sF7[POS + HALO_F];
    __shared__ float swc[512];                     // Wc for fallback

    int tid = threadIdx.x;
    int b   = blockIdx.x >> 5;             // 32 rows
    int t0  = (blockIdx.x & 31) << 7;      // 32 chunks of 128
    unsigned rowbase = (unsigned)b * 4096u;

    ((float4*)swc)[tid] = ((const float4*)Wc)[tid];  // 128 float4 = Wc[8][64]

    // ---- inline token-width detection (self-contained per block) ----------
    // int64 tokens (<1024): odd int32 words are zero high-halves.
    // int32 tokens: words 1..511 are random in [0,1024): P(all 0) ~ 1024^-256.
    unsigned any = tok[2 * tid + 1] | tok[2 * (tid + POS) + 1];
    unsigned stride = __syncthreads_or(any != 0) ? 1u : 2u;

    // ---- token staging ------------------------------------------------------
#pragma unroll
    for (int i = tid; i < POS + 128; i += POS) {
        int t = t0 - 128 + i;
        unsigned v = 0;
        if (t >= 0) v = tok[stride * (rowbase + (unsigned)t)];
        stok[i] = v;
    }
    __syncthreads();

    // ---- F6/F7 block hashes: F(t) = XOR_{r<8} tok(t-1-r)*C(r) ---------------
#pragma unroll
    for (int ft = tid; ft < POS + HALO_F; ft += POS) {
        unsigned f6 = 0, f7 = 0;
#pragma unroll
        for (int q = 0; q < 8; q++) {
            unsigned tk = stok[ft + q];    // token at t-1-r with r = 7-q
            f6 ^= tk * C6(7 - q);
            f7 ^= tk * C7(7 - q);
        }
        sF6[ft] = f6;
        sF7[ft] = f7;
    }

    // ---- scales 0-5 direct --------------------------------------------------
    unsigned hs = 0, h5 = 0;
    unsigned k0 = 0, k1 = 0, k2 = 0, k3 = 0, k4 = 0;
    int basei = 127 + tid;                 // stok index of token at t-1
#pragma unroll
    for (int i = 0; i < 32; i++) {
        unsigned tk = stok[basei - i];
        h5 ^= tk * C5(i);
        if (i < 16) {
            hs ^= tk * BASE(i);
            if (i == 0)  k0 = hs;
            if (i == 1)  k1 = hs;
            if (i == 3)  k2 = hs;
            if (i == 7)  k3 = hs;
            if (i == 15) k4 = hs;
        }
    }
    __syncthreads();

    // ---- scales 6/7 from block hashes ---------------------------------------
    unsigned h6 = 0, h7 = 0;
#pragma unroll
    for (int j = 0; j < 16; j++) {
        h7 ^= sF7[tid + HALO_F - 8 * j];
        if (j < 8) h6 ^= sF6[tid + HALO_F - 8 * j];
    }

    k0 &= 0xFFFFu; k1 &= 0xFFFFu; k2 &= 0xFFFFu; k3 &= 0xFFFFu; k4 &= 0xFFFFu;
    unsigned k5 = h5 & 0xFFFFu, k6 = h6 & 0xFFFFu, k7 = h7 & 0xFFFFu;

    // ---- conditioning logits (fp32 via d_proj, rare exact fallback) ---------
    uint64_t pol = mk_pin_policy();
    float lg[8] = {0.f, 0.f, 0.f, 0.f, 0.f, 0.f, 0.f, 0.f};
    unsigned ks[4] = { k0, k1, k2, k3 };
#pragma unroll
    for (int s = 0; s < 4; s++) {
        const float4* p = ((const float4*)d_proj) + ((size_t)((s << 16) + ks[s])) * 2;
        float4 a = ldg_pin(p, pol), c = ldg_pin(p + 1, pol);
        lg[0] += a.x; lg[1] += a.y; lg[2] += a.z; lg[3] += a.w;
        lg[4] += c.x; lg[5] += c.y; lg[6] += c.z; lg[7] += c.w;
    }
#pragma unroll
    for (int j = 0; j < 8; j++) {
        if (fabsf(lg[j]) < 1e-5f) {
            double acc = 0.0;
#pragma unroll
            for (int s = 0; s < 4; s++) {
                const float* row = tables + ((size_t)((s << 16) + ks[s])) * 16;
                const float* w = &swc[j * 64 + s * 16];
#pragma unroll
                for (int e = 0; e < 16; e++)
                    acc += (double)row[e] * (double)w[e];
            }
            lg[j] = (float)acc;
        }
    }
    unsigned cond = 0;
#pragma unroll
    for (int j = 0; j < 8; j++)
        if (lg[j] > 0.f) cond ^= BASE(j);
    cond &= 0xFFFFu;

    uint4 packed;
    packed.x = k0 | (k1 << 16);
    packed.y = k2 | (k3 << 16);
    packed.z = (k4 ^ cond) | ((k5 ^ cond) << 16);
    packed.w = (k6 ^ cond) | ((k7 ^ cond) << 16);
    d_keys[rowbase + (unsigned)t0 + (unsigned)tid] = packed;
}

// ---------------------------------------------------------------------------
// K3: gather. One warp per position; lane l -> scale s = l>>2, quarter
// q = l&3. Uniform 16 B key load per warp (broadcast), pinned LDG.128
// gather, streaming STG.128 store (512 contiguous bytes per warp).
// ---------------------------------------------------------------------------
__global__ __launch_bounds__(256) void rhp_gather(
    const float* __restrict__ tables, float* __restrict__ out)
{
    int p    = (blockIdx.x << 3) + (threadIdx.x >> 5);   // global position
    int lane = threadIdx.x & 31;
    int s    = lane >> 2;
    int q    = lane & 3;

    uint4 pk = d_keys[p];
    unsigned c2 = (s < 2) ? pk.x : (s < 4) ? pk.y : (s < 6) ? pk.z : pk.w;
    unsigned key = (s & 1) ? (c2 >> 16) : (c2 & 0xFFFFu);

    uint64_t pol = mk_pin_policy();
    const float4* tab4 = (const float4*)tables;
    float4 v = ldg_pin(tab4 + ((size_t)((s << 16) + key) << 2) + q, pol);
    stg_stream(((float4*)out) + (size_t)p * 32 + lane, v);
}

extern "C" void kernel_launch(void* const* d_in, const int* in_sizes, int n_in,
                              void* d_out, int out_size)
{
    const unsigned* tokens = (const unsigned*)d_in[0];
    const float*    tables = (const float*)d_in[1];
    const float*    Wc     = (const float*)d_in[2];
    float*          out    = (float*)d_out;

    rhp_proj<<<1024, 256>>>(tables, Wc);           // 4*65536 rows / 256
    rhp_keys<<<1024, 128>>>(tokens, tables, Wc);   // 32 rows * 32 chunks of 128
    rhp_gather<<<16384, 256>>>(tables, out);       // 131072 positions
}